// round 6
// baseline (speedup 1.0000x reference)
#include <cuda_runtime.h>
#include <cuda_bf16.h>

#define BB 256
#define TT 4096
#define II 63
#define HH 50
#define FCC 64
#define OO 2

// Scratch (static __device__ arrays; no allocation in kernel_launch)
__device__ float g_xz[(size_t)BB * TT * HH];   // [B*T, H] input projection
__device__ float g_hT[BB * HH];                // final hidden states

// ---------------------------------------------------------------------------
// packed fp32x2 FMA (sm_100+)
// ---------------------------------------------------------------------------
__device__ __forceinline__ float2 ffma2(float2 a, float2 b, float2 c) {
    unsigned long long ua, ub, uc, ud;
    ua = *reinterpret_cast<unsigned long long*>(&a);
    ub = *reinterpret_cast<unsigned long long*>(&b);
    uc = *reinterpret_cast<unsigned long long*>(&c);
    asm("fma.rn.f32x2 %0, %1, %2, %3;" : "=l"(ud) : "l"(ua), "l"(ub), "l"(uc));
    return *reinterpret_cast<float2*>(&ud);
}

// fast accurate-enough tanh: 1 - 2/(1+exp(2x)).
// __expf = MUFU.EX2, __fdividef = MUFU.RCP+mul. rel err ~1e-6.
// Saturation: x->+inf: e=inf -> div=0 -> 1.  x->-inf: e=0 -> 1-2 = -1.
__device__ __forceinline__ float fast_tanh(float x) {
    float e = __expf(x + x);
    return 1.0f - __fdividef(2.0f, e + 1.0f);
}

// ---------------------------------------------------------------------------
// Kernel 1: xz = x @ W_ih^T + b_ih.  warp-per-row, lane owns output pair.
// NEW: 4-deep register prefetch ring over rows to hide DRAM latency.
// ---------------------------------------------------------------------------
#define XD 4   // row prefetch depth

__global__ void __launch_bounds__(256, 1)
xz_kernel(const float* __restrict__ x,
          const float* __restrict__ W_ih,
          const float* __restrict__ b_ih) {
    __shared__ float sx[8][128];  // per-warp duplicated x row (126 used)

    const int lane = threadIdx.x & 31;
    const int w    = threadIdx.x >> 5;
    const long long gw = blockIdx.x * 8 + w;   // global warp id
    const long long nw = gridDim.x * 8;        // total warps
    const int jp   = lane;                     // j-pair index, active < 25

    // weight pairs in regs: wr[i] = (W[2jp][i], W[2jp+1][i])
    float2 wr[II];
    float2 bias = make_float2(0.f, 0.f);
    if (jp < 25) {
#pragma unroll
        for (int i = 0; i < II; i++) {
            wr[i].x = __ldg(&W_ih[(2 * jp) * II + i]);
            wr[i].y = __ldg(&W_ih[(2 * jp + 1) * II + i]);
        }
        bias.x = __ldg(&b_ih[2 * jp]);
        bias.y = __ldg(&b_ih[2 * jp + 1]);
    }

    const long long ROWS = (long long)BB * TT;
    float2* sxd = reinterpret_cast<float2*>(sx[w]);

    // --- prefetch ring: each slot holds one x row (2 floats per lane) ---
    float p0[XD], p1[XD];
#pragma unroll
    for (int d = 0; d < XD; d++) {
        long long r = gw + (long long)d * nw;
        const float* xr = x + (r < ROWS ? r : 0) * II;
        p0[d] = __ldg(&xr[lane]);
        p1[d] = (lane < II - 32) ? __ldg(&xr[32 + lane]) : 0.f;
    }

    long long idx = 0;
    for (long long row = gw; row < ROWS; row += nw, idx++) {
        const int s = (int)(idx & (XD - 1));
        const float v0 = p0[s];
        const float v1 = p1[s];

        // issue prefetch for row + XD*nw (in flight during compute)
        {
            long long r = row + (long long)XD * nw;
            const float* xr = x + (r < ROWS ? r : 0) * II;
            p0[s] = __ldg(&xr[lane]);
            p1[s] = (lane < II - 32) ? __ldg(&xr[32 + lane]) : 0.f;
        }

        // stage duplicated: sxd[i] = (x_i, x_i)
        sxd[lane] = make_float2(v0, v0);
        if (lane < II - 32) sxd[32 + lane] = make_float2(v1, v1);
        __syncwarp();

        if (jp < 25) {
            float2 a0 = bias;
            float2 a1 = make_float2(0.f, 0.f);
            const float4* sxp4 = reinterpret_cast<const float4*>(sx[w]);
#pragma unroll
            for (int p = 0; p < 31; p++) {       // i = 2p, 2p+1 (0..61)
                float4 q = sxp4[p];
                a0 = ffma2(make_float2(q.x, q.y), wr[2 * p], a0);
                a1 = ffma2(make_float2(q.z, q.w), wr[2 * p + 1], a1);
            }
            {
                float2 x62 = sxd[62];            // i = 62
                a0 = ffma2(x62, wr[62], a0);
            }
            float2 r2;
            r2.x = a0.x + a1.x;
            r2.y = a0.y + a1.y;
            *reinterpret_cast<float2*>(&g_xz[(size_t)row * HH + 2 * jp]) = r2;
        }
        __syncwarp();
    }
}

// ---------------------------------------------------------------------------
// Kernel 2: sequential scan. ONE row per 64-thread CTA (2 warps), 256 CTAs.
//  - barrier is only 2 warps wide; rows fully decoupled
//  - fast_tanh replaces library tanhf (the old chain killer)
//  - h double-buffered in smem; 8-deep xz register prefetch ring
// ---------------------------------------------------------------------------
#define PF 8

__global__ void __launch_bounds__(64)
scan_kernel(const float* __restrict__ W_hh,
            const float* __restrict__ b_hh) {
    __shared__ float hbuf[2][56];   // 50 used, padded

    const int tid    = threadIdx.x;
    const bool active = (tid < HH);
    const int j      = tid;
    const int row    = blockIdx.x;

    float w[HH];
    float bj = 0.f;
    if (active) {
#pragma unroll
        for (int k = 0; k < HH; k++) w[k] = __ldg(&W_hh[j * HH + k]);
        bj = __ldg(&b_hh[j]);
    }

    if (tid < 56) { hbuf[0][tid] = 0.f; hbuf[1][tid] = 0.f; }

    const float* xzr = g_xz + (size_t)row * TT * HH + (active ? j : 0);

    // xz prefetch ring
    float xzb[PF];
#pragma unroll
    for (int p = 0; p < PF; p++)
        xzb[p] = active ? __ldg(xzr + (size_t)p * HH) : 0.f;

    float hlast = 0.f;
    int cb = 0;
    __syncthreads();

#pragma unroll 4
    for (int t = 0; t < TT; t++) {
        const int slot = t & (PF - 1);
        const float xz_c = xzb[slot];
        if (t + PF < TT)
            xzb[slot] = active ? __ldg(xzr + (size_t)(t + PF) * HH) : 0.f;

        if (active) {
            const float* hp = hbuf[cb];
            float a0 = xz_c + bj;
            float a1 = 0.f, a2 = 0.f, a3 = 0.f;
#pragma unroll
            for (int k4 = 0; k4 < 12; k4++) {
                float4 hv = *reinterpret_cast<const float4*>(hp + 4 * k4);
                a0 = fmaf(hv.x, w[4 * k4 + 0], a0);
                a1 = fmaf(hv.y, w[4 * k4 + 1], a1);
                a2 = fmaf(hv.z, w[4 * k4 + 2], a2);
                a3 = fmaf(hv.w, w[4 * k4 + 3], a3);
            }
            a0 = fmaf(hp[48], w[48], a0);
            a1 = fmaf(hp[49], w[49], a1);
            float pre = (a0 + a1) + (a2 + a3);
            hlast = fast_tanh(pre);
            hbuf[cb ^ 1][j] = hlast;   // writes other buffer; readers use cb
        }
        __syncthreads();
        cb ^= 1;
    }

    if (active) g_hT[row * HH + j] = hlast;
}

// ---------------------------------------------------------------------------
// Kernel 3: MLP head + argmax.  thread per batch row.
// ---------------------------------------------------------------------------
__global__ void __launch_bounds__(64, 1)
head_kernel(const float* __restrict__ W1, const float* __restrict__ b1,
            const float* __restrict__ W2, const float* __restrict__ b2,
            float* __restrict__ out) {
    __shared__ float sW1[FCC * HH];
    __shared__ float sW2[OO * FCC];
    __shared__ float sb1[FCC];
    __shared__ float sb2[OO];

    const int tid = threadIdx.x;
    for (int i = tid; i < FCC * HH; i += blockDim.x) sW1[i] = W1[i];
    for (int i = tid; i < OO * FCC; i += blockDim.x) sW2[i] = W2[i];
    if (tid < FCC) sb1[tid] = b1[tid];
    if (tid < OO)  sb2[tid] = b2[tid];
    __syncthreads();

    const int row = blockIdx.x * blockDim.x + tid;
    if (row >= BB) return;

    float h[HH];
#pragma unroll
    for (int k = 0; k < HH; k++) h[k] = g_hT[row * HH + k];

    float l0 = sb2[0], l1 = sb2[1];
#pragma unroll 4
    for (int f = 0; f < FCC; f++) {
        float d = sb1[f];
#pragma unroll
        for (int k = 0; k < HH; k++) d = fmaf(h[k], sW1[f * HH + k], d);
        d = fmaxf(d, 0.f);
        l0 = fmaf(d, sW2[f], l0);
        l1 = fmaf(d, sW2[FCC + f], l1);
    }
    // softmax monotone; jnp.argmax picks FIRST max -> strict >
    out[row] = (l1 > l0) ? 1.0f : 0.0f;
}

// ---------------------------------------------------------------------------
extern "C" void kernel_launch(void* const* d_in, const int* in_sizes, int n_in,
                              void* d_out, int out_size) {
    const float* x    = (const float*)d_in[0];
    const float* W_ih = (const float*)d_in[1];
    const float* b_ih = (const float*)d_in[2];
    const float* W_hh = (const float*)d_in[3];
    const float* b_hh = (const float*)d_in[4];
    const float* W1   = (const float*)d_in[5];
    const float* b1   = (const float*)d_in[6];
    const float* W2   = (const float*)d_in[7];
    const float* b2   = (const float*)d_in[8];
    float* out = (float*)d_out;

    // 148 CTAs x 8 warps, grid-stride rows with 4-deep prefetch ring
    xz_kernel<<<148, 256>>>(x, W_ih, b_ih);
    // 256 CTAs x 64 threads: one row per CTA, 2-warp barrier, decoupled rows
    scan_kernel<<<256, 64>>>(W_hh, b_hh);
    head_kernel<<<4, 64>>>(W1, b1, W2, b2, out);
}

// round 7
// speedup vs baseline: 2.5359x; 2.5359x over previous
#include <cuda_runtime.h>
#include <cuda_bf16.h>

#define BB 256
#define TT 4096
#define II 63
#define HH 50
#define FCC 64
#define OO 2

// Scratch (static __device__ array; no allocation in kernel_launch)
__device__ float g_hT[BB * HH];   // final hidden states

// ---------------------------------------------------------------------------
// packed fp32x2 FMA (sm_100+): one instruction = two fp32 FMAs
// ---------------------------------------------------------------------------
__device__ __forceinline__ float2 ffma2(float2 a, float2 b, float2 c) {
    unsigned long long ua, ub, uc, ud;
    ua = *reinterpret_cast<unsigned long long*>(&a);
    ub = *reinterpret_cast<unsigned long long*>(&b);
    uc = *reinterpret_cast<unsigned long long*>(&c);
    asm("fma.rn.f32x2 %0, %1, %2, %3;" : "=l"(ud) : "l"(ua), "l"(ub), "l"(uc));
    return *reinterpret_cast<float2*>(&ud);
}

// fast accurate tanh: 1 - 2/(1+exp(2x)); rel err ~1e-6, correct saturation.
__device__ __forceinline__ float fast_tanh(float x) {
    float e = __expf(x + x);
    return 1.0f - __fdividef(2.0f, e + 1.0f);
}

// ---------------------------------------------------------------------------
// FUSED kernel: input projection + sequential scan in one pass.
//   128 CTAs x 128 threads; CTA owns 2 batch rows; thread (lrow, j) owns h_j.
//   x[row][t][:] (252 B contiguous) staged via smem ring (PF steps ahead)
//   fed by a register ring (RD more steps ahead) -> ~2000 cyc LDG cover.
//   xz_j = x . W_ih[j] computed in-step (independent of h -> off the chain).
//   h double-buffered in smem, ONE __syncthreads per step.
// ---------------------------------------------------------------------------
#define PF 8   // smem ring depth (steps)
#define RD 8   // register ring depth (steps)

__global__ void __launch_bounds__(128, 1)
fused_scan_kernel(const float* __restrict__ x,
                  const float* __restrict__ W_ih,
                  const float* __restrict__ b_ih,
                  const float* __restrict__ W_hh,
                  const float* __restrict__ b_hh) {
    __shared__ float xring[PF][2][64];   // [slot][localrow][i], 63 used + pad
    __shared__ float hbuf[2][2][64];     // [buf][localrow][j], 50 used + pad

    const int tid   = threadIdx.x;
    const int lrow  = tid >> 6;          // 0..1
    const int j     = tid & 63;          // 0..63
    const bool active = (j < HH);
    const int grow  = blockIdx.x * 2 + lrow;

    // ---- weights in registers (paired for f32x2) ----
    float2 whp[25];                      // W_hh[j][2k],[2k+1]
    float2 wip[31];                      // W_ih[j][2i],[2i+1]
    float  wi62 = 0.f, bj = 0.f, bi = 0.f;
    if (active) {
#pragma unroll
        for (int k = 0; k < 25; k++) {
            whp[k].x = __ldg(&W_hh[j * HH + 2 * k]);
            whp[k].y = __ldg(&W_hh[j * HH + 2 * k + 1]);
        }
#pragma unroll
        for (int i = 0; i < 31; i++) {
            wip[i].x = __ldg(&W_ih[j * II + 2 * i]);
            wip[i].y = __ldg(&W_ih[j * II + 2 * i + 1]);
        }
        wi62 = __ldg(&W_ih[j * II + 62]);
        bj = __ldg(&b_hh[j]);
        bi = __ldg(&b_ih[j]);
    }

    // ---- loader role: thread -> one x element per step, coalesced ----
    bool loader = false;
    int lr = 0, lc = 0;
    if (tid < II)                  { loader = true; lr = 0; lc = tid; }
    else if (tid >= 64 && tid < 64 + II) { loader = true; lr = 1; lc = tid - 64; }
    const float* xbase = x + (size_t)(blockIdx.x * 2 + lr) * TT * II + lc;

    // ---- init: zero h buffers, prime smem + register rings ----
    ((float*)hbuf)[tid] = 0.f;
    ((float*)hbuf)[tid + 128] = 0.f;

#pragma unroll
    for (int d = 0; d < PF; d++)
        if (loader) xring[d][lr][lc] = __ldg(xbase + (size_t)d * II);

    float rreg[RD];
#pragma unroll
    for (int d = 0; d < RD; d++)
        rreg[d] = loader ? __ldg(xbase + (size_t)(PF + d) * II) : 0.f;

    __syncthreads();

    float hlast = 0.f;
    int cb = 0;

#pragma unroll 4
    for (int t = 0; t < TT; t++) {
        const int slot = t & (PF - 1);
        const int rs   = t & (RD - 1);
        const float xv = rreg[rs];              // holds x[t+PF] (long done)

        // issue LDG for x[t+PF+RD] (completes ~RD steps from now)
        {
            int tl = t + PF + RD;
            if (tl > TT - 1) tl = TT - 1;       // clamped; values never read
            if (loader) rreg[rs] = __ldg(xbase + (size_t)tl * II);
        }

        if (active) {
            // ---- xz_j = x[t] . W_ih[j] + b_ih[j]  (no h dependence) ----
            const float4* xp = reinterpret_cast<const float4*>(xring[slot][lrow]);
            float2 s0 = make_float2(bi, 0.f);
            float2 s1 = make_float2(0.f, 0.f);
#pragma unroll
            for (int p = 0; p < 15; p++) {       // i = 4p .. 4p+3 (0..59)
                float4 q = xp[p];
                s0 = ffma2(make_float2(q.x, q.y), wip[2 * p], s0);
                s1 = ffma2(make_float2(q.z, q.w), wip[2 * p + 1], s1);
            }
            float4 q15 = xp[15];                 // (x60, x61, x62, pad)
            s0 = ffma2(make_float2(q15.x, q15.y), wip[30], s0);
            float xz62 = q15.z * wi62;

            // ---- h . W_hh[j] + b_hh[j] ----
            const float* hp = hbuf[cb][lrow];
            const float4* hp4 = reinterpret_cast<const float4*>(hp);
            float2 a0 = make_float2(bj, 0.f);
            float2 a1 = make_float2(0.f, 0.f);
#pragma unroll
            for (int k = 0; k < 12; k++) {       // h[0..47]
                float4 hv = hp4[k];
                a0 = ffma2(make_float2(hv.x, hv.y), whp[2 * k], a0);
                a1 = ffma2(make_float2(hv.z, hv.w), whp[2 * k + 1], a1);
            }
            float2 h24 = reinterpret_cast<const float2*>(hp)[24];  // h48,h49
            a0 = ffma2(h24, whp[24], a0);

            float pre = ((a0.x + a0.y) + (a1.x + a1.y))
                      + ((s0.x + s0.y) + (s1.x + s1.y) + xz62);
            hlast = fast_tanh(pre);
            hbuf[cb ^ 1][lrow][j] = hlast;
        }
        __syncthreads();

        // refill smem slot with x[t+PF] (readers are PF barriers away)
        if (loader) xring[slot][lr][lc] = xv;
        cb ^= 1;
    }

    if (active) g_hT[grow * HH + j] = hlast;
}

// ---------------------------------------------------------------------------
// MLP head + argmax.  thread per batch row.
// ---------------------------------------------------------------------------
__global__ void __launch_bounds__(64, 1)
head_kernel(const float* __restrict__ W1, const float* __restrict__ b1,
            const float* __restrict__ W2, const float* __restrict__ b2,
            float* __restrict__ out) {
    __shared__ float sW1[FCC * HH];
    __shared__ float sW2[OO * FCC];
    __shared__ float sb1[FCC];
    __shared__ float sb2[OO];

    const int tid = threadIdx.x;
    for (int i = tid; i < FCC * HH; i += blockDim.x) sW1[i] = W1[i];
    for (int i = tid; i < OO * FCC; i += blockDim.x) sW2[i] = W2[i];
    if (tid < FCC) sb1[tid] = b1[tid];
    if (tid < OO)  sb2[tid] = b2[tid];
    __syncthreads();

    const int row = blockIdx.x * blockDim.x + tid;
    if (row >= BB) return;

    float h[HH];
#pragma unroll
    for (int k = 0; k < HH; k++) h[k] = g_hT[row * HH + k];

    float l0 = sb2[0], l1 = sb2[1];
#pragma unroll 4
    for (int f = 0; f < FCC; f++) {
        float d = sb1[f];
#pragma unroll
        for (int k = 0; k < HH; k++) d = fmaf(h[k], sW1[f * HH + k], d);
        d = fmaxf(d, 0.f);
        l0 = fmaf(d, sW2[f], l0);
        l1 = fmaf(d, sW2[FCC + f], l1);
    }
    // softmax monotone; jnp.argmax picks FIRST max -> strict >
    out[row] = (l1 > l0) ? 1.0f : 0.0f;
}

// ---------------------------------------------------------------------------
extern "C" void kernel_launch(void* const* d_in, const int* in_sizes, int n_in,
                              void* d_out, int out_size) {
    const float* x    = (const float*)d_in[0];
    const float* W_ih = (const float*)d_in[1];
    const float* b_ih = (const float*)d_in[2];
    const float* W_hh = (const float*)d_in[3];
    const float* b_hh = (const float*)d_in[4];
    const float* W1   = (const float*)d_in[5];
    const float* b1   = (const float*)d_in[6];
    const float* W2   = (const float*)d_in[7];
    const float* b2   = (const float*)d_in[8];
    float* out = (float*)d_out;

    // fused input-projection + scan: 128 CTAs x 128 thr, 2 rows/CTA,
    // 1 CTA/SM, 1 warp/SMSP. No g_xz materialization at all.
    fused_scan_kernel<<<128, 128>>>(x, W_ih, b_ih, W_hh, b_hh);
    head_kernel<<<4, 64>>>(W1, b1, W2, b2, out);
}

// round 9
// speedup vs baseline: 5.2983x; 2.0893x over previous
#include <cuda_runtime.h>
#include <cuda_bf16.h>

#define BB 256
#define TT 4096
#define II 63
#define HH 50
#define FCC 64
#define OO 2
#define CH 8            // steps per chunk (producer->consumer sync grain)
#define NC (TT / CH)    // 512 chunks

// Scratch (static __device__ array; no allocation in kernel_launch)
__device__ float g_hT[BB * HH];

// packed fp32x2 FMA (sm_100+)
__device__ __forceinline__ float2 ffma2(float2 a, float2 b, float2 c) {
    unsigned long long ua, ub, uc, ud;
    ua = *reinterpret_cast<unsigned long long*>(&a);
    ub = *reinterpret_cast<unsigned long long*>(&b);
    uc = *reinterpret_cast<unsigned long long*>(&c);
    asm("fma.rn.f32x2 %0, %1, %2, %3;" : "=l"(ud) : "l"(ua), "l"(ub), "l"(uc));
    return *reinterpret_cast<float2*>(&ud);
}

// 2*log2(e): folded into weights so tanh needs no input scaling
#define TSCALE 2.885390081777926814f

// tanh(x) where p = 2*log2(e)*x already: tanh = 1 - 2/(1 + 2^p)
// ex2/rcp.approx: same HW units as __expf/__fdividef (passed rel_err 0.0 before)
__device__ __forceinline__ float tanh_scaled(float p) {
    float e, r;
    asm("ex2.approx.f32 %0, %1;" : "=f"(e) : "f"(p));
    asm("rcp.approx.f32 %0, %1;" : "=f"(r) : "f"(e + 1.0f));
    return fmaf(-2.0f, r, 1.0f);
}

// ---------------------------------------------------------------------------
// Warp-specialized fused kernel. 128 CTAs x 128 threads, CTA owns 2 rows.
//  warp 0: recurrence for row 0   (lane p owns h[2p], h[2p+1])
//  warp 1: recurrence for row 1
//  warp 2: xz producer j=0..31  + x loader row 0
//  warp 3: xz producer j=32..49 + x loader row 1
// xz staged CH=8 steps ahead (2-slot ring); x staged 3 chunks ahead (4-slot
// ring) via LDG->reg->STS pipeline. Consumers sync per-step with __syncwarp
// ONLY; full __syncthreads once per 8 steps.
// ---------------------------------------------------------------------------
__global__ void __launch_bounds__(128, 1)
fused_scan_kernel(const float* __restrict__ x,
                  const float* __restrict__ W_ih,
                  const float* __restrict__ b_ih,
                  const float* __restrict__ W_hh,
                  const float* __restrict__ b_hh) {
    __shared__ float xs[4][2][CH * 64];     // x ring: [chunk&3][row][t*64+i], 16KB
    __shared__ float xzs[2][2][CH][64];     // xz ring: [chunk&1][row][s][j], 8KB
    __shared__ float hb[2][2][64];          // h double buffer: [cb][row][j]

    const int tid  = threadIdx.x;
    const int wid  = tid >> 5;
    const int lane = tid & 31;

    // zero h buffers (all threads, before any barrier)
    ((float*)hb)[tid]       = 0.f;
    ((float*)hb)[tid + 128] = 0.f;

    if (wid < 2) {
        // ======================= CONSUMER (recurrence) =======================
        const int crow = wid;
        const int p    = lane;
        const int j0   = (p < 25) ? 2 * p : 48;   // clamp idle lanes

        float2 w0[25], w1[25];
#pragma unroll
        for (int m = 0; m < 25; m++) {
            w0[m].x = TSCALE * __ldg(&W_hh[j0 * HH + 2 * m]);
            w0[m].y = TSCALE * __ldg(&W_hh[j0 * HH + 2 * m + 1]);
            w1[m].x = TSCALE * __ldg(&W_hh[(j0 + 1) * HH + 2 * m]);
            w1[m].y = TSCALE * __ldg(&W_hh[(j0 + 1) * HH + 2 * m + 1]);
        }
        const float bh0 = TSCALE * __ldg(&b_hh[j0]);
        const float bh1 = TSCALE * __ldg(&b_hh[j0 + 1]);

        __syncthreads();   // matches producer barrier #1 (x chunks 0,1 staged)
        __syncthreads();   // matches producer barrier #2 (xz chunk 0 ready)

        for (int c = 0; c < NC; c++) {
            const float* xzrow = &xzs[c & 1][crow][0][0];
#pragma unroll
            for (int s = 0; s < CH; s++) {
                float2 xzp = *(const float2*)(xzrow + s * 64 + 2 * p);
                const float*  hp  = hb[s & 1][crow];
                const float4* hp4 = (const float4*)hp;
                float2 a0 = make_float2(xzp.x + bh0, 0.f);
                float2 a1 = make_float2(0.f, 0.f);
                float2 c0 = make_float2(xzp.y + bh1, 0.f);
                float2 c1 = make_float2(0.f, 0.f);
#pragma unroll
                for (int m = 0; m < 12; m++) {
                    float4 hq = hp4[m];
                    float2 hA = make_float2(hq.x, hq.y);
                    float2 hB = make_float2(hq.z, hq.w);
                    a0 = ffma2(hA, w0[2 * m], a0);
                    a1 = ffma2(hB, w0[2 * m + 1], a1);
                    c0 = ffma2(hA, w1[2 * m], c0);
                    c1 = ffma2(hB, w1[2 * m + 1], c1);
                }
                float2 h24 = ((const float2*)hp)[24];   // h48,h49
                a0 = ffma2(h24, w0[24], a0);
                c0 = ffma2(h24, w1[24], c0);
                float pre0 = (a0.x + a0.y) + (a1.x + a1.y);
                float pre1 = (c0.x + c0.y) + (c1.x + c1.y);
                float hn0 = tanh_scaled(pre0);
                float hn1 = tanh_scaled(pre1);
                if (p < 25)
                    *(float2*)&hb[(s & 1) ^ 1][crow][2 * p] = make_float2(hn0, hn1);
                __syncwarp();
            }
            __syncthreads();   // phase boundary (xz ring flip)
        }

        if (p < 25) {
            const int grow = blockIdx.x * 2 + crow;
            float2 hv = *(const float2*)&hb[0][crow][2 * p];
            g_hT[grow * HH + 2 * p]     = hv.x;
            g_hT[grow * HH + 2 * p + 1] = hv.y;
        }
    } else {
        // ==================== PRODUCER (xz) + LOADER (x) =====================
        const int prow = wid - 2;                       // loader row
        const int pj   = (wid == 2) ? lane : 32 + lane; // produced j
        const int pjc  = (pj < HH) ? pj : HH - 1;

        float2 wip[31];
#pragma unroll
        for (int i = 0; i < 31; i++) {
            wip[i].x = TSCALE * __ldg(&W_ih[pjc * II + 2 * i]);
            wip[i].y = TSCALE * __ldg(&W_ih[pjc * II + 2 * i + 1]);
        }
        const float wi62 = TSCALE * __ldg(&W_ih[pjc * II + 62]);
        const float bi   = TSCALE * __ldg(&b_ih[pjc]);

        const float* xldbase = x + (size_t)(blockIdx.x * 2 + prow) * TT * II;

        // per-lane loader pattern: f = q*32+lane covers 504 floats per chunk
        int offq[16], fqv[16];
#pragma unroll
        for (int q = 0; q < 16; q++) {
            int f = q * 32 + lane;
            fqv[q] = f;
            int t  = f / 63;
            offq[q] = t * 64 + (f - 63 * t);   // padded [t][i] layout
        }

        // xz for one t from staged x (row pointer pre-offset)
        auto dotx = [&](const float* xr) -> float {
            const float4* xp4 = (const float4*)xr;
            float2 u0 = make_float2(bi, 0.f);
            float2 u1 = make_float2(0.f, 0.f);
#pragma unroll
            for (int n = 0; n < 15; n++) {
                float4 q = xp4[n];
                u0 = ffma2(make_float2(q.x, q.y), wip[2 * n], u0);
                u1 = ffma2(make_float2(q.z, q.w), wip[2 * n + 1], u1);
            }
            float4 q15 = xp4[15];   // x60,x61,x62,(pad unused)
            u0 = ffma2(make_float2(q15.x, q15.y), wip[30], u0);
            return (u0.x + u0.y) + (u1.x + u1.y) + q15.z * wi62;
        };

        float rld[16];
        // ---- prologue: chunks 0,1 -> smem; chunk 2 -> regs ----
#pragma unroll
        for (int q = 0; q < 16; q++)
            if (fqv[q] < CH * II) rld[q] = __ldg(xldbase + fqv[q]);
#pragma unroll
        for (int q = 0; q < 16; q++)
            if (fqv[q] < CH * II) xs[0][prow][offq[q]] = rld[q];
#pragma unroll
        for (int q = 0; q < 16; q++)
            if (fqv[q] < CH * II) rld[q] = __ldg(xldbase + CH * II + fqv[q]);
#pragma unroll
        for (int q = 0; q < 16; q++)
            if (fqv[q] < CH * II) xs[1][prow][offq[q]] = rld[q];
#pragma unroll
        for (int q = 0; q < 16; q++)
            if (fqv[q] < CH * II) rld[q] = __ldg(xldbase + 2 * CH * II + fqv[q]);
        __syncthreads();   // barrier #1: x chunks 0,1 visible

        // xz chunk 0
        {
            const float* x0 = &xs[0][0][0];
            const float* x1 = &xs[0][1][0];
#pragma unroll 4
            for (int s = 0; s < CH; s++) {
                float v0 = dotx(x0 + s * 64);
                float v1 = dotx(x1 + s * 64);
                if (pj < HH) {
                    xzs[0][0][s][pj] = v0;
                    xzs[0][1][s][pj] = v1;
                }
            }
        }
        __syncthreads();   // barrier #2: xz chunk 0 ready

        for (int c = 0; c < NC; c++) {
            // stage x chunk c+2 (regs loaded one phase ago -> landed)
            if (c + 2 < NC) {
#pragma unroll
                for (int q = 0; q < 16; q++)
                    if (fqv[q] < CH * II) xs[(c + 2) & 3][prow][offq[q]] = rld[q];
            }
            // issue LDG for x chunk c+3 (lands within next phase)
            if (c + 3 < NC) {
#pragma unroll
                for (int q = 0; q < 16; q++)
                    if (fqv[q] < CH * II)
                        rld[q] = __ldg(xldbase + (size_t)(c + 3) * CH * II + fqv[q]);
            }
            // compute xz chunk c+1 while consumers chew chunk c
            if (c + 1 < NC) {
                const float* x0 = &xs[(c + 1) & 3][0][0];
                const float* x1 = &xs[(c + 1) & 3][1][0];
                float* z0 = &xzs[(c + 1) & 1][0][0][0];
                float* z1 = &xzs[(c + 1) & 1][1][0][0];
#pragma unroll 4
                for (int s = 0; s < CH; s++) {
                    float v0 = dotx(x0 + s * 64);
                    float v1 = dotx(x1 + s * 64);
                    if (pj < HH) {
                        z0[s * 64 + pj] = v0;
                        z1[s * 64 + pj] = v1;
                    }
                }
            }
            __syncthreads();   // phase boundary
        }
    }
}

// ---------------------------------------------------------------------------
// MLP head + argmax.  thread per batch row.
// ---------------------------------------------------------------------------
__global__ void __launch_bounds__(64, 1)
head_kernel(const float* __restrict__ W1, const float* __restrict__ b1,
            const float* __restrict__ W2, const float* __restrict__ b2,
            float* __restrict__ out) {
    __shared__ float sW1[FCC * HH];
    __shared__ float sW2[OO * FCC];
    __shared__ float sb1[FCC];
    __shared__ float sb2[OO];

    const int tid = threadIdx.x;
    for (int i = tid; i < FCC * HH; i += blockDim.x) sW1[i] = W1[i];
    for (int i = tid; i < OO * FCC; i += blockDim.x) sW2[i] = W2[i];
    if (tid < FCC) sb1[tid] = b1[tid];
    if (tid < OO)  sb2[tid] = b2[tid];
    __syncthreads();

    const int row = blockIdx.x * blockDim.x + tid;
    if (row >= BB) return;

    float h[HH];
#pragma unroll
    for (int k = 0; k < HH; k++) h[k] = g_hT[row * HH + k];

    float l0 = sb2[0], l1 = sb2[1];
#pragma unroll 4
    for (int f = 0; f < FCC; f++) {
        float d = sb1[f];
#pragma unroll
        for (int k = 0; k < HH; k++) d = fmaf(h[k], sW1[f * HH + k], d);
        d = fmaxf(d, 0.f);
        l0 = fmaf(d, sW2[f], l0);
        l1 = fmaf(d, sW2[FCC + f], l1);
    }
    // softmax monotone; jnp.argmax picks FIRST max -> strict >
    out[row] = (l1 > l0) ? 1.0f : 0.0f;
}

// ---------------------------------------------------------------------------
extern "C" void kernel_launch(void* const* d_in, const int* in_sizes, int n_in,
                              void* d_out, int out_size) {
    const float* x    = (const float*)d_in[0];
    const float* W_ih = (const float*)d_in[1];
    const float* b_ih = (const float*)d_in[2];
    const float* W_hh = (const float*)d_in[3];
    const float* b_hh = (const float*)d_in[4];
    const float* W1   = (const float*)d_in[5];
    const float* b1   = (const float*)d_in[6];
    const float* W2   = (const float*)d_in[7];
    const float* b2   = (const float*)d_in[8];
    float* out = (float*)d_out;

    // warp-specialized fused scan: 128 CTAs x 128 thr, 2 rows/CTA, 1 CTA/SM;
    // consumer warps on SMSP0/1, producer/loader warps on SMSP2/3.
    fused_scan_kernel<<<128, 128>>>(x, W_ih, b_ih, W_hh, b_hh);
    head_kernel<<<4, 64>>>(W1, b1, W2, b2, out);
}